// round 10
// baseline (speedup 1.0000x reference)
#include <cuda_runtime.h>
#include <cstdint>

#define NUM_CLASSES 17929
#define BATCH       512
#define NUM_MODELS  16
#define HIDDEN      4

#define TPB         512
#define TILE_C      512            // classes per CTA (== TPB)
#define RPC         128            // batch rows per CTA (grid.y = 4)
#define NT          128            // tiles per CTA (1 batch row per tile)
#define STAGES      6
#define PLANES      NUM_MODELS                   // 16 (one row per model)
#define PADW        516                          // 512 + shift(<=3) + pad -> 2064B (16B mult.)
#define PLANE_BYTES (PADW * 4)                   // 2064
#define STAGE_FLOATS (PLANES * PADW)             // 8256
#define STAGE_BYTES  (STAGE_FLOATS * 4)          // 33024
#define MBAR_OFF    0
#define DATA_OFF    64                           // stages start 16B-aligned after mbarriers
#define SMEM_BYTES  (DATA_OFF + STAGES * STAGE_BYTES)   // 198208
#define TILE_TX     (PLANES * PLANE_BYTES)       // 33024 bytes per tile

__device__ __forceinline__ void mbar_init(uint32_t addr, uint32_t count) {
    asm volatile("mbarrier.init.shared.b64 [%0], %1;" :: "r"(addr), "r"(count) : "memory");
}
__device__ __forceinline__ void mbar_arrive_expect(uint32_t addr, uint32_t bytes) {
    asm volatile("mbarrier.arrive.expect_tx.shared.b64 _, [%0], %1;"
                 :: "r"(addr), "r"(bytes) : "memory");
}
__device__ __forceinline__ void mbar_wait(uint32_t addr, uint32_t parity) {
    uint32_t done;
    asm volatile(
        "{\n\t.reg .pred p;\n\t"
        "mbarrier.try_wait.parity.acquire.cta.shared::cta.b64 p, [%1], %2;\n\t"
        "selp.b32 %0, 1, 0, p;\n\t}"
        : "=r"(done) : "r"(addr), "r"(parity) : "memory");
    if (!done) {
        asm volatile(
            "{\n\t.reg .pred P1;\n\t"
            "WAIT_LOOP_%=:\n\t"
            "mbarrier.try_wait.parity.acquire.cta.shared::cta.b64 P1, [%0], %1, 0x989680;\n\t"
            "@P1 bra.uni WAIT_DONE_%=;\n\t"
            "bra.uni WAIT_LOOP_%=;\n\t"
            "WAIT_DONE_%=:\n\t}"
            :: "r"(addr), "r"(parity) : "memory");
    }
}
__device__ __forceinline__ void bulk_copy(uint32_t dst, const void* src,
                                          uint32_t bytes, uint32_t mbar) {
    asm volatile(
        "cp.async.bulk.shared::cta.global.mbarrier::complete_tx::bytes [%0], [%1], %2, [%3];"
        :: "r"(dst), "l"(src), "r"(bytes), "r"(mbar) : "memory");
}

extern __shared__ float smem[];

__global__ void __launch_bounds__(TPB, 1)
family_mlp_kernel(const float* __restrict__ x,     // [M, B, C]
                  const float* __restrict__ W1,    // [C, H, M]
                  const float* __restrict__ b1,    // [C, H]
                  const float* __restrict__ W2,    // [C, H]
                  const float* __restrict__ b2,    // [C]
                  float* __restrict__ out)         // [B, C]
{
    const int tid = threadIdx.x;
    int c0 = blockIdx.x * TILE_C;
    if (c0 > NUM_CLASSES - TILE_C) c0 = NUM_CLASSES - TILE_C;   // overlap last block
    const int c04 = c0 & 3;
    const int c   = c0 + tid;
    const int r0  = blockIdx.y * RPC;

    // ---- per-class weights in registers ----
    float w1[HIDDEN][NUM_MODELS];
    {
        const float4* wv = reinterpret_cast<const float4*>(W1) + (size_t)c * 16;
        #pragma unroll
        for (int k = 0; k < 16; ++k) {
            float4 v = __ldg(wv + k);
            const int h = k >> 2, mm = (k & 3) * 4;
            w1[h][mm + 0] = v.x; w1[h][mm + 1] = v.y;
            w1[h][mm + 2] = v.z; w1[h][mm + 3] = v.w;
        }
    }
    const float4 bb1 = __ldg(reinterpret_cast<const float4*>(b1) + c);
    const float4 ww2 = __ldg(reinterpret_cast<const float4*>(W2) + c);
    const float  bb2 = __ldg(b2 + c);

    const size_t plane = (size_t)BATCH * NUM_CLASSES;
    float* obase = out + (size_t)r0 * NUM_CLASSES + c;

    uint32_t sbase;
    asm("{ .reg .u64 t; cvta.to.shared.u64 t, %1; cvt.u32.u64 %0, t; }"
        : "=r"(sbase) : "l"(smem));
    const uint32_t mbar0 = sbase + MBAR_OFF;
    const uint32_t data0 = sbase + DATA_OFF;

    // issue one tile: 16 bulk copies of one batch row across all model planes
    auto issue_tile = [&](int t) {
        const uint32_t mb = mbar0 + (t % STAGES) * 8;
        if (tid == 0) mbar_arrive_expect(mb, TILE_TX);
        if (tid < PLANES) {
            const int a = (c04 + t) & 3;             // row misalignment (same for all m)
            const float* src = x + (size_t)tid * plane
                                 + (size_t)(r0 + t) * NUM_CLASSES + (c0 - a);
            const uint32_t dst = data0 + (t % STAGES) * STAGE_BYTES + tid * PLANE_BYTES;
            bulk_copy(dst, src, PLANE_BYTES, mb);
        }
    };

    // ---- init mbarriers, then fill the pipeline ----
    if (tid == 0) {
        #pragma unroll
        for (int s = 0; s < STAGES; ++s) mbar_init(mbar0 + s * 8, 1);
    }
    __syncthreads();
    #pragma unroll
    for (int t = 0; t < STAGES - 1; ++t) issue_tile(t);   // tiles 0..4

    #pragma unroll 1
    for (int t = 0; t < NT; ++t) {
        mbar_wait(mbar0 + (t % STAGES) * 8, (t / STAGES) & 1);

        const int a = (c04 + t) & 3;
        const float* buf = smem + (DATA_OFF / 4) + (t % STAGES) * STAGE_FLOATS + tid + a;

        float h0 = bb1.x, h1 = bb1.y, h2 = bb1.z, h3 = bb1.w;
        #pragma unroll
        for (int m = 0; m < NUM_MODELS; ++m) {
            const float v = buf[m * PADW];
            h0 = fmaf(v, w1[0][m], h0);
            h1 = fmaf(v, w1[1][m], h1);
            h2 = fmaf(v, w1[2][m], h2);
            h3 = fmaf(v, w1[3][m], h3);
        }
        float acc = bb2;
        acc = fmaf(fmaxf(h0, 0.0f), ww2.x, acc);
        acc = fmaf(fmaxf(h1, 0.0f), ww2.y, acc);
        acc = fmaf(fmaxf(h2, 0.0f), ww2.z, acc);
        acc = fmaf(fmaxf(h3, 0.0f), ww2.w, acc);
        __stcs(obase + (size_t)t * NUM_CLASSES, acc);

        __syncthreads();   // everyone finished tile t -> stage (t-1)%S reusable
        if (t + STAGES - 1 < NT) issue_tile(t + STAGES - 1);
    }
}

extern "C" void kernel_launch(void* const* d_in, const int* in_sizes, int n_in,
                              void* d_out, int out_size)
{
    const float* x  = (const float*)d_in[0];   // [16, 512, 17929]
    const float* W1 = (const float*)d_in[1];   // [17929, 4, 16]
    const float* b1 = (const float*)d_in[2];   // [17929, 4]
    const float* W2 = (const float*)d_in[3];   // [17929, 4]
    const float* b2 = (const float*)d_in[4];   // [17929]
    float* out = (float*)d_out;                // [512, 17929]

    cudaFuncSetAttribute(family_mlp_kernel,
                         cudaFuncAttributeMaxDynamicSharedMemorySize, SMEM_BYTES);

    dim3 grid((NUM_CLASSES + TILE_C - 1) / TILE_C, BATCH / RPC);   // 36 x 4 = 144 CTAs
    family_mlp_kernel<<<grid, TPB, SMEM_BYTES>>>(x, W1, b1, W2, b2, out);
}

// round 11
// speedup vs baseline: 1.1363x; 1.1363x over previous
#include <cuda_runtime.h>
#include <cstdint>

#define NUM_CLASSES 17929
#define BATCH       512
#define NUM_MODELS  16
#define HIDDEN      4

#define TPB         256
#define TILE_C      256            // classes per CTA (== TPB)
#define BT          2              // batch rows per tile
#define RPC         128            // batch rows per CTA (grid.y = 4)
#define NT          (RPC / BT)     // 64 tiles per CTA
#define STAGES      3
#define PLANES      (NUM_MODELS * BT)            // 32 copies per tile
#define PADW        260                          // 256 + shift(<=3) + pad -> 1040B (16B mult.)
#define PLANE_BYTES (PADW * 4)                   // 1040
#define STAGE_FLOATS (PLANES * PADW)             // 8320
#define STAGE_BYTES  (STAGE_FLOATS * 4)          // 33280
#define MBAR_OFF    0
#define DATA_OFF    64
#define SMEM_BYTES  (DATA_OFF + STAGES * STAGE_BYTES)   // 99904 -> 2 CTAs/SM
#define TILE_TX     (PLANES * PLANE_BYTES)       // 33280

__device__ __forceinline__ void mbar_init(uint32_t addr, uint32_t count) {
    asm volatile("mbarrier.init.shared.b64 [%0], %1;" :: "r"(addr), "r"(count) : "memory");
}
__device__ __forceinline__ void mbar_arrive_expect(uint32_t addr, uint32_t bytes) {
    asm volatile("mbarrier.arrive.expect_tx.shared.b64 _, [%0], %1;"
                 :: "r"(addr), "r"(bytes) : "memory");
}
__device__ __forceinline__ void mbar_wait(uint32_t addr, uint32_t parity) {
    uint32_t done;
    asm volatile(
        "{\n\t.reg .pred p;\n\t"
        "mbarrier.try_wait.parity.acquire.cta.shared::cta.b64 p, [%1], %2;\n\t"
        "selp.b32 %0, 1, 0, p;\n\t}"
        : "=r"(done) : "r"(addr), "r"(parity) : "memory");
    if (!done) {
        asm volatile(
            "{\n\t.reg .pred P1;\n\t"
            "WAIT_LOOP_%=:\n\t"
            "mbarrier.try_wait.parity.acquire.cta.shared::cta.b64 P1, [%0], %1, 0x989680;\n\t"
            "@P1 bra.uni WAIT_DONE_%=;\n\t"
            "bra.uni WAIT_LOOP_%=;\n\t"
            "WAIT_DONE_%=:\n\t}"
            :: "r"(addr), "r"(parity) : "memory");
    }
}
__device__ __forceinline__ void bulk_copy(uint32_t dst, const void* src,
                                          uint32_t bytes, uint32_t mbar) {
    asm volatile(
        "cp.async.bulk.shared::cta.global.mbarrier::complete_tx::bytes [%0], [%1], %2, [%3];"
        :: "r"(dst), "l"(src), "r"(bytes), "r"(mbar) : "memory");
}

extern __shared__ float smem[];

__global__ void __launch_bounds__(TPB, 2)
family_mlp_kernel(const float* __restrict__ x,     // [M, B, C]
                  const float* __restrict__ W1,    // [C, H, M]
                  const float* __restrict__ b1,    // [C, H]
                  const float* __restrict__ W2,    // [C, H]
                  const float* __restrict__ b2,    // [C]
                  float* __restrict__ out)         // [B, C]
{
    const int tid = threadIdx.x;
    int c0 = blockIdx.x * TILE_C;
    if (c0 > NUM_CLASSES - TILE_C) c0 = NUM_CLASSES - TILE_C;   // overlap last block
    const int c04 = c0 & 3;
    const int c   = c0 + tid;
    const int r0  = blockIdx.y * RPC;

    // ---- per-class weights in registers ----
    float w1[HIDDEN][NUM_MODELS];
    {
        const float4* wv = reinterpret_cast<const float4*>(W1) + (size_t)c * 16;
        #pragma unroll
        for (int k = 0; k < 16; ++k) {
            float4 v = __ldg(wv + k);
            const int h = k >> 2, mm = (k & 3) * 4;
            w1[h][mm + 0] = v.x; w1[h][mm + 1] = v.y;
            w1[h][mm + 2] = v.z; w1[h][mm + 3] = v.w;
        }
    }
    const float4 bb1 = __ldg(reinterpret_cast<const float4*>(b1) + c);
    const float4 ww2 = __ldg(reinterpret_cast<const float4*>(W2) + c);
    const float  bb2 = __ldg(b2 + c);

    const size_t plane = (size_t)BATCH * NUM_CLASSES;
    float* obase = out + (size_t)r0 * NUM_CLASSES + c;

    uint32_t sbase;
    asm("{ .reg .u64 t; cvta.to.shared.u64 t, %1; cvt.u32.u64 %0, t; }"
        : "=r"(sbase) : "l"(smem));
    const uint32_t mbar0 = sbase + MBAR_OFF;
    const uint32_t data0 = sbase + DATA_OFF;

    // issue one tile: 32 bulk copies (16 models x 2 rows), threads 0..31, one each
    auto issue_tile = [&](int t) {
        const uint32_t mb = mbar0 + (t % STAGES) * 8;
        if (tid == 0) mbar_arrive_expect(mb, TILE_TX);
        if (tid < PLANES) {
            const int m = tid >> 1, b = tid & 1;
            const int row = 2 * t + b;
            const int a = (c04 + row) & 3;          // row-start misalignment, model-indep.
            const float* src = x + (size_t)m * plane
                                 + (size_t)(r0 + row) * NUM_CLASSES + (c0 - a);
            const uint32_t dst = data0 + (t % STAGES) * STAGE_BYTES + tid * PLANE_BYTES;
            bulk_copy(dst, src, PLANE_BYTES, mb);
        }
    };

    // ---- init mbarriers, then fill pipeline ----
    if (tid == 0) {
        #pragma unroll
        for (int s = 0; s < STAGES; ++s) mbar_init(mbar0 + s * 8, 1);
    }
    __syncthreads();
    issue_tile(0);
    issue_tile(1);

    #pragma unroll 1
    for (int t = 0; t < NT; ++t) {
        mbar_wait(mbar0 + (t % STAGES) * 8, (t / STAGES) & 1);

        const int stage = t % STAGES;
        const float* sb = smem + (DATA_OFF / 4) + stage * STAGE_FLOATS;

        #pragma unroll
        for (int b = 0; b < BT; ++b) {
            const int a = (c04 + 2 * t + b) & 3;
            const float* buf = sb + b * PADW + tid + a;    // m-stride = 2*PADW

            float h0 = bb1.x, h1 = bb1.y, h2 = bb1.z, h3 = bb1.w;
            #pragma unroll
            for (int m = 0; m < NUM_MODELS; ++m) {
                const float v = buf[m * (2 * PADW)];
                h0 = fmaf(v, w1[0][m], h0);
                h1 = fmaf(v, w1[1][m], h1);
                h2 = fmaf(v, w1[2][m], h2);
                h3 = fmaf(v, w1[3][m], h3);
            }
            float acc = bb2;
            acc = fmaf(fmaxf(h0, 0.0f), ww2.x, acc);
            acc = fmaf(fmaxf(h1, 0.0f), ww2.y, acc);
            acc = fmaf(fmaxf(h2, 0.0f), ww2.z, acc);
            acc = fmaf(fmaxf(h3, 0.0f), ww2.w, acc);
            __stcs(obase + (size_t)(2 * t + b) * NUM_CLASSES, acc);
        }

        __syncthreads();   // all consumed tile t -> its stage reusable by issue below
        if (t + STAGES - 1 < NT) issue_tile(t + STAGES - 1);
    }
}

extern "C" void kernel_launch(void* const* d_in, const int* in_sizes, int n_in,
                              void* d_out, int out_size)
{
    const float* x  = (const float*)d_in[0];   // [16, 512, 17929]
    const float* W1 = (const float*)d_in[1];   // [17929, 4, 16]
    const float* b1 = (const float*)d_in[2];   // [17929, 4]
    const float* W2 = (const float*)d_in[3];   // [17929, 4]
    const float* b2 = (const float*)d_in[4];   // [17929]
    float* out = (float*)d_out;                // [512, 17929]

    cudaFuncSetAttribute(family_mlp_kernel,
                         cudaFuncAttributeMaxDynamicSharedMemorySize, SMEM_BYTES);

    dim3 grid((NUM_CLASSES + TILE_C - 1) / TILE_C, BATCH / RPC);   // 71 x 4 = 284 CTAs
    family_mlp_kernel<<<grid, TPB, SMEM_BYTES>>>(x, W1, b1, W2, b2, out);
}

// round 12
// speedup vs baseline: 1.1408x; 1.0040x over previous
#include <cuda_runtime.h>
#include <cstdint>

#define NUM_CLASSES 17929
#define BATCH       512
#define NUM_MODELS  16
#define HIDDEN      4

#define TPB         256
#define TILE_C      256            // classes per CTA (== TPB)
#define BT          2              // batch rows per tile
#define RPC         128            // batch rows per CTA (grid.y = 4)
#define NT          (RPC / BT)     // 64 tiles per CTA
#define STAGES      3
#define PLANES      (NUM_MODELS * BT)            // 32 copies per tile
#define PADW        260                          // 256 + shift(<=3) + pad -> 1040B (16B mult.)
#define PLANE_BYTES (PADW * 4)                   // 1040
#define STAGE_FLOATS (PLANES * PADW)             // 8320
#define STAGE_BYTES  (STAGE_FLOATS * 4)          // 33280
#define MBAR_OFF    0
#define DATA_OFF    64
#define SMEM_BYTES  (DATA_OFF + STAGES * STAGE_BYTES)   // 99904 -> 2 CTAs/SM
#define TILE_TX     (PLANES * PLANE_BYTES)       // 33280

__device__ __forceinline__ void mbar_init(uint32_t addr, uint32_t count) {
    asm volatile("mbarrier.init.shared.b64 [%0], %1;" :: "r"(addr), "r"(count) : "memory");
}
__device__ __forceinline__ void mbar_arrive_expect(uint32_t addr, uint32_t bytes) {
    asm volatile("mbarrier.arrive.expect_tx.shared.b64 _, [%0], %1;"
                 :: "r"(addr), "r"(bytes) : "memory");
}
__device__ __forceinline__ void mbar_wait(uint32_t addr, uint32_t parity) {
    uint32_t done;
    asm volatile(
        "{\n\t.reg .pred p;\n\t"
        "mbarrier.try_wait.parity.acquire.cta.shared::cta.b64 p, [%1], %2;\n\t"
        "selp.b32 %0, 1, 0, p;\n\t}"
        : "=r"(done) : "r"(addr), "r"(parity) : "memory");
    if (!done) {
        asm volatile(
            "{\n\t.reg .pred P1;\n\t"
            "WAIT_LOOP_%=:\n\t"
            "mbarrier.try_wait.parity.acquire.cta.shared::cta.b64 P1, [%0], %1, 0x989680;\n\t"
            "@P1 bra.uni WAIT_DONE_%=;\n\t"
            "bra.uni WAIT_LOOP_%=;\n\t"
            "WAIT_DONE_%=:\n\t}"
            :: "r"(addr), "r"(parity) : "memory");
    }
}
__device__ __forceinline__ void bulk_copy(uint32_t dst, const void* src,
                                          uint32_t bytes, uint32_t mbar) {
    asm volatile(
        "cp.async.bulk.shared::cta.global.mbarrier::complete_tx::bytes [%0], [%1], %2, [%3];"
        :: "r"(dst), "l"(src), "r"(bytes), "r"(mbar) : "memory");
}

extern __shared__ float smem[];

__global__ void __launch_bounds__(TPB, 2)
family_mlp_kernel(const float* __restrict__ x,     // [M, B, C]
                  const float* __restrict__ W1,    // [C, H, M]
                  const float* __restrict__ b1,    // [C, H]
                  const float* __restrict__ W2,    // [C, H]
                  const float* __restrict__ b2,    // [C]
                  float* __restrict__ out)         // [B, C]
{
    const int tid = threadIdx.x;
    int c0 = blockIdx.x * TILE_C;
    if (c0 > NUM_CLASSES - TILE_C) c0 = NUM_CLASSES - TILE_C;   // overlap last block
    const int c04 = c0 & 3;
    const int c   = c0 + tid;
    const int r0  = blockIdx.y * RPC;

    // ---- per-class weights in registers ----
    float w1[HIDDEN][NUM_MODELS];
    {
        const float4* wv = reinterpret_cast<const float4*>(W1) + (size_t)c * 16;
        #pragma unroll
        for (int k = 0; k < 16; ++k) {
            float4 v = __ldg(wv + k);
            const int h = k >> 2, mm = (k & 3) * 4;
            w1[h][mm + 0] = v.x; w1[h][mm + 1] = v.y;
            w1[h][mm + 2] = v.z; w1[h][mm + 3] = v.w;
        }
    }
    const float4 bb1 = __ldg(reinterpret_cast<const float4*>(b1) + c);
    const float4 ww2 = __ldg(reinterpret_cast<const float4*>(W2) + c);
    const float  bb2 = __ldg(b2 + c);

    const size_t plane = (size_t)BATCH * NUM_CLASSES;
    float* obase = out + (size_t)r0 * NUM_CLASSES + c;

    uint32_t sbase;
    asm("{ .reg .u64 t; cvta.to.shared.u64 t, %1; cvt.u32.u64 %0, t; }"
        : "=r"(sbase) : "l"(smem));
    const uint32_t mbar0 = sbase + MBAR_OFF;
    const uint32_t data0 = sbase + DATA_OFF;

    // issue one tile: 32 bulk copies (16 models x 2 rows), threads 0..31, one each
    auto issue_tile = [&](int t) {
        const uint32_t mb = mbar0 + (t % STAGES) * 8;
        if (tid == 0) mbar_arrive_expect(mb, TILE_TX);
        if (tid < PLANES) {
            const int m = tid >> 1, b = tid & 1;
            const int row = 2 * t + b;
            const int a = (c04 + row) & 3;          // row-start misalignment, model-indep.
            const float* src = x + (size_t)m * plane
                                 + (size_t)(r0 + row) * NUM_CLASSES + (c0 - a);
            const uint32_t dst = data0 + (t % STAGES) * STAGE_BYTES + tid * PLANE_BYTES;
            bulk_copy(dst, src, PLANE_BYTES, mb);
        }
    };

    // ---- init mbarriers, then fill pipeline ----
    if (tid == 0) {
        #pragma unroll
        for (int s = 0; s < STAGES; ++s) mbar_init(mbar0 + s * 8, 1);
    }
    __syncthreads();
    issue_tile(0);
    issue_tile(1);

    #pragma unroll 1
    for (int t = 0; t < NT; ++t) {
        mbar_wait(mbar0 + (t % STAGES) * 8, (t / STAGES) & 1);
        // Barrier FIRST: everyone passed wait(t) => everyone finished compute(t-1)
        // => stage (t+2)%3 == (t-1)%3 is fully consumed and safe to overwrite.
        __syncthreads();
        // Issue BEFORE compute: keeps 2 tiles in the DMA queue during the whole
        // compute phase instead of 1 (the R10 saw-tooth).
        if (t + STAGES - 1 < NT) issue_tile(t + STAGES - 1);

        const int stage = t % STAGES;
        const float* sb = smem + (DATA_OFF / 4) + stage * STAGE_FLOATS;

        #pragma unroll
        for (int b = 0; b < BT; ++b) {
            const int a = (c04 + 2 * t + b) & 3;
            const float* buf = sb + b * PADW + tid + a;    // m-stride = 2*PADW

            float h0 = bb1.x, h1 = bb1.y, h2 = bb1.z, h3 = bb1.w;
            #pragma unroll
            for (int m = 0; m < NUM_MODELS; ++m) {
                const float v = buf[m * (2 * PADW)];
                h0 = fmaf(v, w1[0][m], h0);
                h1 = fmaf(v, w1[1][m], h1);
                h2 = fmaf(v, w1[2][m], h2);
                h3 = fmaf(v, w1[3][m], h3);
            }
            float acc = bb2;
            acc = fmaf(fmaxf(h0, 0.0f), ww2.x, acc);
            acc = fmaf(fmaxf(h1, 0.0f), ww2.y, acc);
            acc = fmaf(fmaxf(h2, 0.0f), ww2.z, acc);
            acc = fmaf(fmaxf(h3, 0.0f), ww2.w, acc);
            __stcs(obase + (size_t)(2 * t + b) * NUM_CLASSES, acc);
        }
    }
}

extern "C" void kernel_launch(void* const* d_in, const int* in_sizes, int n_in,
                              void* d_out, int out_size)
{
    const float* x  = (const float*)d_in[0];   // [16, 512, 17929]
    const float* W1 = (const float*)d_in[1];   // [17929, 4, 16]
    const float* b1 = (const float*)d_in[2];   // [17929, 4]
    const float* W2 = (const float*)d_in[3];   // [17929, 4]
    const float* b2 = (const float*)d_in[4];   // [17929]
    float* out = (float*)d_out;                // [512, 17929]

    cudaFuncSetAttribute(family_mlp_kernel,
                         cudaFuncAttributeMaxDynamicSharedMemorySize, SMEM_BYTES);

    dim3 grid((NUM_CLASSES + TILE_C - 1) / TILE_C, BATCH / RPC);   // 71 x 4 = 284 CTAs
    family_mlp_kernel<<<grid, TPB, SMEM_BYTES>>>(x, W1, b1, W2, b2, out);
}